// round 5
// baseline (speedup 1.0000x reference)
#include <cuda_runtime.h>
#include <math.h>

#define NMAX 1024
#define SMAX 256
#define L2E 1.4426950408889634f
#define TTHR 1.0e-4f
#define ECUT -26.6f
#define NBLOCKS 152

typedef unsigned long long ull;

// Per-gaussian params (unsorted, indexed by original gaussian id)
__device__ float4 g_cull[NMAX];   // mx, my, cut2, z_bits(as float)
__device__ float4 g_p0[NMAX];     // mx, my, A, B
__device__ float4 g_p1[NMAX];     // C, la, cr, cg
__device__ float  g_cb[NMAX];     // blue
__device__ int    g_tile_ctr;     // dynamic tile queue head

// ---------------------------------------------------------------------------
// Kernel 1: per-gaussian precompute (parallel grid) + queue reset
// ---------------------------------------------------------------------------
__global__ void precompute_kernel(const float* __restrict__ mean,
                                  const float* __restrict__ qvec,
                                  const float* __restrict__ svecb,
                                  const float* __restrict__ sh,
                                  const float* __restrict__ alphab,
                                  const float* __restrict__ c2w,
                                  int N)
{
    int n = blockIdx.x * blockDim.x + threadIdx.x;
    if (n == 0) g_tile_ctr = 0;
    if (n >= N) return;

    float cw[16];
#pragma unroll
    for (int i = 0; i < 16; i++) cw[i] = __ldg(c2w + i);

    float d0 = mean[3 * n + 0] - cw[3];
    float d1 = mean[3 * n + 1] - cw[7];
    float d2 = mean[3 * n + 2] - cw[11];
    float px = cw[0] * d0 + cw[4] * d1 + cw[8]  * d2;
    float py = cw[1] * d0 + cw[5] * d1 + cw[9]  * d2;
    float pz = cw[2] * d0 + cw[6] * d1 + cw[10] * d2;

    float z = fmaxf(pz, 0.001f);
    float mx = px / z;
    float my = py / z;

    float qw = qvec[4 * n + 0], qx = qvec[4 * n + 1], qy = qvec[4 * n + 2], qz = qvec[4 * n + 3];
    float qn = rsqrtf(qw * qw + qx * qx + qy * qy + qz * qz);
    qw *= qn; qx *= qn; qy *= qn; qz *= qn;
    float R00 = 1.f - 2.f * (qy * qy + qz * qz);
    float R01 = 2.f * (qx * qy - qw * qz);
    float R02 = 2.f * (qx * qz + qw * qy);
    float R10 = 2.f * (qx * qy + qw * qz);
    float R11 = 1.f - 2.f * (qx * qx + qz * qz);
    float R12 = 2.f * (qy * qz - qw * qx);
    float R20 = 2.f * (qx * qz - qw * qy);
    float R21 = 2.f * (qy * qz + qw * qx);
    float R22 = 1.f - 2.f * (qx * qx + qy * qy);

    float s0 = expf(svecb[3 * n + 0]);
    float s1 = expf(svecb[3 * n + 1]);
    float s2 = expf(svecb[3 * n + 2]);

    float M00 = R00 * s0, M01 = R01 * s1, M02 = R02 * s2;
    float M10 = R10 * s0, M11 = R11 * s1, M12 = R12 * s2;
    float M20 = R20 * s0, M21 = R21 * s1, M22 = R22 * s2;
    float v00 = M00 * M00 + M01 * M01 + M02 * M02;
    float v01 = M00 * M10 + M01 * M11 + M02 * M12;
    float v02 = M00 * M20 + M01 * M21 + M02 * M22;
    float v11 = M10 * M10 + M11 * M11 + M12 * M12;
    float v12 = M10 * M20 + M11 * M21 + M12 * M22;
    float v22 = M20 * M20 + M21 * M21 + M22 * M22;

    float W00 = cw[0], W01 = cw[4], W02 = cw[8];
    float W10 = cw[1], W11 = cw[5], W12 = cw[9];
    float W20 = cw[2], W21 = cw[6], W22 = cw[10];

    float t00 = W00 * v00 + W01 * v01 + W02 * v02;
    float t01 = W00 * v01 + W01 * v11 + W02 * v12;
    float t02 = W00 * v02 + W01 * v12 + W02 * v22;
    float t10 = W10 * v00 + W11 * v01 + W12 * v02;
    float t11 = W10 * v01 + W11 * v11 + W12 * v12;
    float t12 = W10 * v02 + W11 * v12 + W12 * v22;
    float t20 = W20 * v00 + W21 * v01 + W22 * v02;
    float t21 = W20 * v01 + W21 * v11 + W22 * v12;
    float t22 = W20 * v02 + W21 * v12 + W22 * v22;

    float c00 = t00 * W00 + t01 * W01 + t02 * W02;
    float c01 = t00 * W10 + t01 * W11 + t02 * W12;
    float c02 = t00 * W20 + t01 * W21 + t02 * W22;
    float c11 = t10 * W10 + t11 * W11 + t12 * W12;
    float c12 = t10 * W20 + t11 * W21 + t12 * W22;
    float c22 = t20 * W20 + t21 * W21 + t22 * W22;

    float iz = 1.f / z;
    float iz2 = iz * iz;
    float j02 = -px * iz2;
    float j12 = -py * iz2;
    float r0a = iz * c00 + j02 * c02;
    float r0b = iz * c01 + j02 * c12;
    float r0c = iz * c02 + j02 * c22;
    float r1b = iz * c11 + j12 * c12;
    float r1c = iz * c12 + j12 * c22;
    float a2d = r0a * iz + r0c * j02 + 1e-8f;
    float b2d = r0b * iz + r0c * j12;
    float c2d = r1b * iz + r1c * j12 + 1e-8f;

    float det = a2d * c2d - b2d * b2d;
    float ia = c2d / det;
    float ib = -b2d / det;
    float ic = a2d / det;

    float A = -0.5f * L2E * ia;
    float B = -L2E * ib;
    float C = -0.5f * L2E * ic;

    float alpha = 1.f / (1.f + expf(-alphab[n]));
    float la = log2f(alpha);

    float mid = 0.5f * (ia + ic);
    float dif = 0.5f * (ia - ic);
    float disc = sqrtf(fmaxf(dif * dif + ib * ib, 0.f));
    float lam = mid - disc;
    float cut2 = (la <= ECUT) ? -1.f
                              : (la - ECUT) / (0.5f * L2E * fmaxf(lam, 1e-30f));

    const float SHB = 0.28209479177387814f;
    float cr = 1.f / (1.f + expf(-SHB * sh[n * 27 + 0]));
    float cg = 1.f / (1.f + expf(-SHB * sh[n * 27 + 9]));
    float cb = 1.f / (1.f + expf(-SHB * sh[n * 27 + 18]));

    g_cull[n] = make_float4(mx, my, cut2, __uint_as_float(__float_as_uint(z)));
    g_p0[n]   = make_float4(mx, my, A, B);
    g_p1[n]   = make_float4(C, la, cr, cg);
    g_cb[n]   = cb;
}

// ---------------------------------------------------------------------------
// Kernel 2: persistent blocks, dynamic tile queue.
// Per tile: cull -> rank sort (2 barriers) -> composite (chunked).
// ---------------------------------------------------------------------------
__global__ void __launch_bounds__(256) render_kernel(float* __restrict__ out,
                                                     int H, int W, int N,
                                                     int ntx, int nty)
{
    __shared__ ull    skey[NMAX];     // 8KB
    __shared__ float4 f0[SMAX];       // 4KB
    __shared__ float4 f1[SMAX];       // 4KB
    __shared__ float  fcb[SMAX];      // 1KB
    __shared__ int    s_w[9];
    __shared__ int    s_tile;

    int tid = threadIdx.x;
    int lane = tid & 31;
    int wid = tid >> 5;
    int tx = tid & 15;
    int ty = tid >> 4;
    int nTiles = ntx * nty;
    float invW = 1.f / (float)W;

    for (;;) {
        __syncthreads();
        if (tid == 0) s_tile = atomicAdd(&g_tile_ctr, 1);
        __syncthreads();
        int tile = s_tile;
        if (tile >= nTiles) break;
        int tbx = tile % ntx;
        int tby = tile / ntx;

        int pxi = tbx * 16 + tx;
        int pyi = tby * 16 + ty;
        float pxc = ((float)pxi + 0.5f - 0.5f * (float)W) * invW;
        float pyc = ((float)pyi + 0.5f - 0.5f * (float)H) * invW;
        float xmin = ((float)(tbx * 16)      + 0.5f - 0.5f * (float)W) * invW;
        float xmax = ((float)(tbx * 16 + 15) + 0.5f - 0.5f * (float)W) * invW;
        float ymin = ((float)(tby * 16)      + 0.5f - 0.5f * (float)H) * invW;
        float ymax = ((float)(tby * 16 + 15) + 0.5f - 0.5f * (float)H) * invW;

        // ---- cull: 4 contiguous gaussians per thread ----
        ull lk[4];
        int li[4];
        int cnt = 0;
#pragma unroll
        for (int r = 0; r < 4; r++) {
            int i = tid * 4 + r;
            if (i < N) {
                float4 c = g_cull[i];
                float ddx = fmaxf(fmaxf(xmin - c.x, c.x - xmax), 0.f);
                float ddy = fmaxf(fmaxf(ymin - c.y, c.y - ymax), 0.f);
                if (ddx * ddx + ddy * ddy <= c.z) {
                    lk[cnt] = ((ull)__float_as_uint(c.w) << 32) | (unsigned)i;
                    li[cnt] = i;
                    cnt++;
                }
            }
        }

        // ---- block exclusive scan ----
        int incl = cnt;
#pragma unroll
        for (int d = 1; d < 32; d <<= 1) {
            int v = __shfl_up_sync(0xFFFFFFFFu, incl, d);
            if (lane >= d) incl += v;
        }
        if (lane == 31) s_w[wid] = incl;
        __syncthreads();
        if (tid == 0) {
            int s = 0;
#pragma unroll
            for (int w = 0; w < 8; w++) { int v = s_w[w]; s_w[w] = s; s += v; }
            s_w[8] = s;
        }
        __syncthreads();
        int base = s_w[wid] + incl - cnt;
        int total = s_w[8];

        for (int j = 0; j < cnt; j++) skey[base + j] = lk[j];
        __syncthreads();

        // ---- ranks (keys unique -> permutation) ----
        int rk[4];
        for (int j = 0; j < cnt; j++) {
            ull mine = lk[j];
            int r = 0;
            for (int k = 0; k < total; k++) r += (skey[k] < mine);
            rk[j] = r;
        }

        // ---- chunked staged composite ----
        float T = 1.f, ar = 0.f, ag = 0.f, ab = 0.f;
        for (int cbase = 0; cbase < total; cbase += SMAX) {
            int cn = min(SMAX, total - cbase);
            for (int j = 0; j < cnt; j++) {
                int r = rk[j] - cbase;
                if ((unsigned)r < (unsigned)SMAX) {
                    int idx = li[j];
                    f0[r]  = g_p0[idx];
                    f1[r]  = g_p1[idx];
                    fcb[r] = g_cb[idx];
                }
            }
            __syncthreads();

            if (T > TTHR) {
                int Me = cn & ~1;
                int k = 0;
                for (; k < Me; k += 2) {
                    float4 p0a = f0[k],     p1a = f1[k];
                    float4 p0b = f0[k + 1], p1b = f1[k + 1];
                    float cba = fcb[k], cbb = fcb[k + 1];
                    float dxa = pxc - p0a.x, dya = pyc - p0a.y;
                    float dxb = pxc - p0b.x, dyb = pyc - p0b.y;
                    float ea = fmaf(p0a.z * dxa, dxa, fmaf(p0a.w * dxa, dya, p1a.x * dya * dya)) + p1a.y;
                    float eb = fmaf(p0b.z * dxb, dxb, fmaf(p0b.w * dxb, dyb, p1b.x * dyb * dyb)) + p1b.y;
                    float wa, wb;
                    asm("ex2.approx.ftz.f32 %0, %1;" : "=f"(wa) : "f"(ea));
                    asm("ex2.approx.ftz.f32 %0, %1;" : "=f"(wb) : "f"(eb));
                    float wTa = wa * T;
                    ar = fmaf(wTa, p1a.z, ar);
                    ag = fmaf(wTa, p1a.w, ag);
                    ab = fmaf(wTa, cba, ab);
                    float T1 = T * (1.f - fminf(wa, 0.9999f));
                    if (T1 > TTHR) {
                        float wTb = wb * T1;
                        ar = fmaf(wTb, p1b.z, ar);
                        ag = fmaf(wTb, p1b.w, ag);
                        ab = fmaf(wTb, cbb, ab);
                        T = T1 * (1.f - fminf(wb, 0.9999f));
                        if (T <= TTHR) break;
                    } else {
                        T = T1;
                        break;
                    }
                }
                if (k == Me && Me < cn && T > TTHR) {
                    float4 p0a = f0[Me], p1a = f1[Me];
                    float cba = fcb[Me];
                    float dxa = pxc - p0a.x, dya = pyc - p0a.y;
                    float ea = fmaf(p0a.z * dxa, dxa, fmaf(p0a.w * dxa, dya, p1a.x * dya * dya)) + p1a.y;
                    float wa;
                    asm("ex2.approx.ftz.f32 %0, %1;" : "=f"(wa) : "f"(ea));
                    float wTa = wa * T;
                    ar = fmaf(wTa, p1a.z, ar);
                    ag = fmaf(wTa, p1a.w, ag);
                    ab = fmaf(wTa, cba, ab);
                    T = T * (1.f - fminf(wa, 0.9999f));
                }
            }
            if (__syncthreads_and(T <= TTHR)) break;
        }

        if (pxi < W && pyi < H) {
            int o = (pyi * W + pxi) * 3;
            out[o + 0] = ar;
            out[o + 1] = ag;
            out[o + 2] = ab;
        }
    }
}

// ---------------------------------------------------------------------------
extern "C" void kernel_launch(void* const* d_in, const int* in_sizes, int n_in,
                              void* d_out, int out_size)
{
    const float* mean  = (const float*)d_in[0];
    const float* qvec  = (const float*)d_in[1];
    const float* svecb = (const float*)d_in[2];
    const float* sh    = (const float*)d_in[3];
    const float* alphb = (const float*)d_in[4];
    const float* c2w   = (const float*)d_in[5];

    int N = in_sizes[0] / 3;
    if (N > NMAX) N = NMAX;
    int HW = out_size / 3;
    int W = (int)(sqrtf((float)HW) + 0.5f);
    int H = HW / W;

    int ntx = (W + 15) / 16;
    int nty = (H + 15) / 16;

    precompute_kernel<<<(N + 255) / 256, 256>>>(mean, qvec, svecb, sh, alphb, c2w, N);
    int nb = ntx * nty;
    if (nb > NBLOCKS) nb = NBLOCKS;
    render_kernel<<<nb, 256>>>((float*)d_out, H, W, N, ntx, nty);
}

// round 6
// speedup vs baseline: 1.3208x; 1.3208x over previous
#include <cuda_runtime.h>
#include <math.h>

#define NMAX 1024
#define SMAX 256
#define L2E 1.4426950408889634f
#define TTHR 1.0e-4f
#define ECUT -26.6f

typedef unsigned long long ull;

// Per-gaussian params (unsorted, indexed by original gaussian id)
__device__ float4 g_cull[NMAX];   // mx, my, cut2, z_bits(as float)
__device__ float4 g_p0[NMAX];     // mx, my, A, B
__device__ float4 g_p1[NMAX];     // C, la, cr, cg
__device__ float  g_cb[NMAX];     // blue
__device__ int    g_arrive;       // grid barrier (zero-init, self-resetting)
__device__ int    g_depart;

// ---------------------------------------------------------------------------
__device__ __forceinline__ void precompute_one(
    int n,
    const float* __restrict__ mean,
    const float* __restrict__ qvec,
    const float* __restrict__ svecb,
    const float* __restrict__ sh,
    const float* __restrict__ alphab,
    const float* __restrict__ c2w)
{
    float cw[16];
#pragma unroll
    for (int i = 0; i < 16; i++) cw[i] = __ldg(c2w + i);

    float d0 = mean[3 * n + 0] - cw[3];
    float d1 = mean[3 * n + 1] - cw[7];
    float d2 = mean[3 * n + 2] - cw[11];
    float px = cw[0] * d0 + cw[4] * d1 + cw[8]  * d2;
    float py = cw[1] * d0 + cw[5] * d1 + cw[9]  * d2;
    float pz = cw[2] * d0 + cw[6] * d1 + cw[10] * d2;

    float z = fmaxf(pz, 0.001f);
    float mx = px / z;
    float my = py / z;

    float qw = qvec[4 * n + 0], qx = qvec[4 * n + 1], qy = qvec[4 * n + 2], qz = qvec[4 * n + 3];
    float qn = rsqrtf(qw * qw + qx * qx + qy * qy + qz * qz);
    qw *= qn; qx *= qn; qy *= qn; qz *= qn;
    float R00 = 1.f - 2.f * (qy * qy + qz * qz);
    float R01 = 2.f * (qx * qy - qw * qz);
    float R02 = 2.f * (qx * qz + qw * qy);
    float R10 = 2.f * (qx * qy + qw * qz);
    float R11 = 1.f - 2.f * (qx * qx + qz * qz);
    float R12 = 2.f * (qy * qz - qw * qx);
    float R20 = 2.f * (qx * qz - qw * qy);
    float R21 = 2.f * (qy * qz + qw * qx);
    float R22 = 1.f - 2.f * (qx * qx + qy * qy);

    float s0 = expf(svecb[3 * n + 0]);
    float s1 = expf(svecb[3 * n + 1]);
    float s2 = expf(svecb[3 * n + 2]);

    float M00 = R00 * s0, M01 = R01 * s1, M02 = R02 * s2;
    float M10 = R10 * s0, M11 = R11 * s1, M12 = R12 * s2;
    float M20 = R20 * s0, M21 = R21 * s1, M22 = R22 * s2;
    float v00 = M00 * M00 + M01 * M01 + M02 * M02;
    float v01 = M00 * M10 + M01 * M11 + M02 * M12;
    float v02 = M00 * M20 + M01 * M21 + M02 * M22;
    float v11 = M10 * M10 + M11 * M11 + M12 * M12;
    float v12 = M10 * M20 + M11 * M21 + M12 * M22;
    float v22 = M20 * M20 + M21 * M21 + M22 * M22;

    float W00 = cw[0], W01 = cw[4], W02 = cw[8];
    float W10 = cw[1], W11 = cw[5], W12 = cw[9];
    float W20 = cw[2], W21 = cw[6], W22 = cw[10];

    float t00 = W00 * v00 + W01 * v01 + W02 * v02;
    float t01 = W00 * v01 + W01 * v11 + W02 * v12;
    float t02 = W00 * v02 + W01 * v12 + W02 * v22;
    float t10 = W10 * v00 + W11 * v01 + W12 * v02;
    float t11 = W10 * v01 + W11 * v11 + W12 * v12;
    float t12 = W10 * v02 + W11 * v12 + W12 * v22;
    float t20 = W20 * v00 + W21 * v01 + W22 * v02;
    float t21 = W20 * v01 + W21 * v11 + W22 * v12;
    float t22 = W20 * v02 + W21 * v12 + W22 * v22;

    float c00 = t00 * W00 + t01 * W01 + t02 * W02;
    float c01 = t00 * W10 + t01 * W11 + t02 * W12;
    float c02 = t00 * W20 + t01 * W21 + t02 * W22;
    float c11 = t10 * W10 + t11 * W11 + t12 * W12;
    float c12 = t10 * W20 + t11 * W21 + t12 * W22;
    float c22 = t20 * W20 + t21 * W21 + t22 * W22;

    float iz = 1.f / z;
    float iz2 = iz * iz;
    float j02 = -px * iz2;
    float j12 = -py * iz2;
    float r0a = iz * c00 + j02 * c02;
    float r0b = iz * c01 + j02 * c12;
    float r0c = iz * c02 + j02 * c22;
    float r1b = iz * c11 + j12 * c12;
    float r1c = iz * c12 + j12 * c22;
    float a2d = r0a * iz + r0c * j02 + 1e-8f;
    float b2d = r0b * iz + r0c * j12;
    float c2d = r1b * iz + r1c * j12 + 1e-8f;

    float det = a2d * c2d - b2d * b2d;
    float ia = c2d / det;
    float ib = -b2d / det;
    float ic = a2d / det;

    float A = -0.5f * L2E * ia;
    float B = -L2E * ib;
    float C = -0.5f * L2E * ic;

    float alpha = 1.f / (1.f + expf(-alphab[n]));
    float la = log2f(alpha);

    float mid = 0.5f * (ia + ic);
    float dif = 0.5f * (ia - ic);
    float disc = sqrtf(fmaxf(dif * dif + ib * ib, 0.f));
    float lam = mid - disc;
    float cut2 = (la <= ECUT) ? -1.f
                              : (la - ECUT) / (0.5f * L2E * fmaxf(lam, 1e-30f));

    const float SHB = 0.28209479177387814f;
    float cr = 1.f / (1.f + expf(-SHB * sh[n * 27 + 0]));
    float cg = 1.f / (1.f + expf(-SHB * sh[n * 27 + 9]));
    float cb = 1.f / (1.f + expf(-SHB * sh[n * 27 + 18]));

    g_cull[n] = make_float4(mx, my, cut2, __uint_as_float(__float_as_uint(z)));
    g_p0[n]   = make_float4(mx, my, A, B);
    g_p1[n]   = make_float4(C, la, cr, cg);
    g_cb[n]   = cb;
}

// ---------------------------------------------------------------------------
// Fused kernel: blocks 0..3 precompute, grid spin-barrier, then every block
// renders its own 16x16 tile (R4 path: cull -> scan -> rank sort -> composite).
// All 256 blocks are co-resident (2/SM needed) so the spin barrier is safe.
// ---------------------------------------------------------------------------
__global__ void __launch_bounds__(256) fused_kernel(
    float* __restrict__ out,
    const float* __restrict__ mean,
    const float* __restrict__ qvec,
    const float* __restrict__ svecb,
    const float* __restrict__ sh,
    const float* __restrict__ alphab,
    const float* __restrict__ c2w,
    int H, int W, int N)
{
    __shared__ ull    skey[NMAX];     // 8KB
    __shared__ float4 f0[SMAX];       // 4KB
    __shared__ float4 f1[SMAX];       // 4KB
    __shared__ float  fcb[SMAX];      // 1KB
    __shared__ int    s_w[9];

    int tid = threadIdx.x;
    int bid = blockIdx.y * gridDim.x + blockIdx.x;
    int nBlocks = gridDim.x * gridDim.y;

    // ---- phase 1: precompute (first 1024 threads of the grid) ----
    if (bid < 4) {
        int n = bid * 256 + tid;
        if (n < N) precompute_one(n, mean, qvec, svecb, sh, alphab, c2w);
    }

    // ---- grid-wide spin barrier ----
    __syncthreads();
    if (tid == 0) {
        __threadfence();
        atomicAdd(&g_arrive, 1);
        while (*(volatile int*)&g_arrive < nBlocks) __nanosleep(64);
    }
    __syncthreads();

    // ---- phase 2: render this block's tile ----
    int lane = tid & 31;
    int wid = tid >> 5;
    int tx = tid & 15;
    int ty = tid >> 4;
    int tbx = blockIdx.x;
    int tby = blockIdx.y;
    int pxi = tbx * 16 + tx;
    int pyi = tby * 16 + ty;

    float invW = 1.f / (float)W;
    float pxc = ((float)pxi + 0.5f - 0.5f * (float)W) * invW;
    float pyc = ((float)pyi + 0.5f - 0.5f * (float)H) * invW;
    float xmin = ((float)(tbx * 16)      + 0.5f - 0.5f * (float)W) * invW;
    float xmax = ((float)(tbx * 16 + 15) + 0.5f - 0.5f * (float)W) * invW;
    float ymin = ((float)(tby * 16)      + 0.5f - 0.5f * (float)H) * invW;
    float ymax = ((float)(tby * 16 + 15) + 0.5f - 0.5f * (float)H) * invW;

    // ---- cull: 4 contiguous gaussians per thread ----
    ull lk[4];
    int li[4];
    int cnt = 0;
#pragma unroll
    for (int r = 0; r < 4; r++) {
        int i = tid * 4 + r;
        if (i < N) {
            float4 c = g_cull[i];
            float ddx = fmaxf(fmaxf(xmin - c.x, c.x - xmax), 0.f);
            float ddy = fmaxf(fmaxf(ymin - c.y, c.y - ymax), 0.f);
            if (ddx * ddx + ddy * ddy <= c.z) {
                lk[cnt] = ((ull)__float_as_uint(c.w) << 32) | (unsigned)i;
                li[cnt] = i;
                cnt++;
            }
        }
    }

    // ---- block exclusive scan ----
    int incl = cnt;
#pragma unroll
    for (int d = 1; d < 32; d <<= 1) {
        int v = __shfl_up_sync(0xFFFFFFFFu, incl, d);
        if (lane >= d) incl += v;
    }
    if (lane == 31) s_w[wid] = incl;
    __syncthreads();
    if (tid == 0) {
        int s = 0;
#pragma unroll
        for (int w = 0; w < 8; w++) { int v = s_w[w]; s_w[w] = s; s += v; }
        s_w[8] = s;
    }
    __syncthreads();
    int base = s_w[wid] + incl - cnt;
    int total = s_w[8];

    for (int j = 0; j < cnt; j++) skey[base + j] = lk[j];
    __syncthreads();

    // ---- ranks (keys unique -> permutation) ----
    int rk[4];
    for (int j = 0; j < cnt; j++) {
        ull mine = lk[j];
        int r = 0;
        for (int k = 0; k < total; k++) r += (skey[k] < mine);
        rk[j] = r;
    }

    // ---- chunked staged composite ----
    float T = 1.f, ar = 0.f, ag = 0.f, ab = 0.f;
    for (int cbase = 0; cbase < total; cbase += SMAX) {
        int cn = min(SMAX, total - cbase);
        for (int j = 0; j < cnt; j++) {
            int r = rk[j] - cbase;
            if ((unsigned)r < (unsigned)SMAX) {
                int idx = li[j];
                f0[r]  = g_p0[idx];
                f1[r]  = g_p1[idx];
                fcb[r] = g_cb[idx];
            }
        }
        __syncthreads();

        if (T > TTHR) {
            int Me = cn & ~1;
            int k = 0;
            for (; k < Me; k += 2) {
                float4 p0a = f0[k],     p1a = f1[k];
                float4 p0b = f0[k + 1], p1b = f1[k + 1];
                float cba = fcb[k], cbb = fcb[k + 1];
                float dxa = pxc - p0a.x, dya = pyc - p0a.y;
                float dxb = pxc - p0b.x, dyb = pyc - p0b.y;
                float ea = fmaf(p0a.z * dxa, dxa, fmaf(p0a.w * dxa, dya, p1a.x * dya * dya)) + p1a.y;
                float eb = fmaf(p0b.z * dxb, dxb, fmaf(p0b.w * dxb, dyb, p1b.x * dyb * dyb)) + p1b.y;
                float wa, wb;
                asm("ex2.approx.ftz.f32 %0, %1;" : "=f"(wa) : "f"(ea));
                asm("ex2.approx.ftz.f32 %0, %1;" : "=f"(wb) : "f"(eb));
                float wTa = wa * T;
                ar = fmaf(wTa, p1a.z, ar);
                ag = fmaf(wTa, p1a.w, ag);
                ab = fmaf(wTa, cba, ab);
                float T1 = T * (1.f - fminf(wa, 0.9999f));
                if (T1 > TTHR) {
                    float wTb = wb * T1;
                    ar = fmaf(wTb, p1b.z, ar);
                    ag = fmaf(wTb, p1b.w, ag);
                    ab = fmaf(wTb, cbb, ab);
                    T = T1 * (1.f - fminf(wb, 0.9999f));
                    if (T <= TTHR) break;
                } else {
                    T = T1;
                    break;
                }
            }
            if (k == Me && Me < cn && T > TTHR) {
                float4 p0a = f0[Me], p1a = f1[Me];
                float cba = fcb[Me];
                float dxa = pxc - p0a.x, dya = pyc - p0a.y;
                float ea = fmaf(p0a.z * dxa, dxa, fmaf(p0a.w * dxa, dya, p1a.x * dya * dya)) + p1a.y;
                float wa;
                asm("ex2.approx.ftz.f32 %0, %1;" : "=f"(wa) : "f"(ea));
                float wTa = wa * T;
                ar = fmaf(wTa, p1a.z, ar);
                ag = fmaf(wTa, p1a.w, ag);
                ab = fmaf(wTa, cba, ab);
                T = T * (1.f - fminf(wa, 0.9999f));
            }
        }
        if (__syncthreads_and(T <= TTHR)) break;
    }

    if (pxi < W && pyi < H) {
        int o = (pyi * W + pxi) * 3;
        out[o + 0] = ar;
        out[o + 1] = ag;
        out[o + 2] = ab;
    }

    // ---- self-resetting barrier counters (last block out zeroes both) ----
    if (tid == 0) {
        int d = atomicAdd(&g_depart, 1);
        if (d == nBlocks - 1) {
            *(volatile int*)&g_arrive = 0;
            *(volatile int*)&g_depart = 0;
            __threadfence();
        }
    }
}

// ---------------------------------------------------------------------------
extern "C" void kernel_launch(void* const* d_in, const int* in_sizes, int n_in,
                              void* d_out, int out_size)
{
    const float* mean  = (const float*)d_in[0];
    const float* qvec  = (const float*)d_in[1];
    const float* svecb = (const float*)d_in[2];
    const float* sh    = (const float*)d_in[3];
    const float* alphb = (const float*)d_in[4];
    const float* c2w   = (const float*)d_in[5];

    int N = in_sizes[0] / 3;
    if (N > NMAX) N = NMAX;
    int HW = out_size / 3;
    int W = (int)(sqrtf((float)HW) + 0.5f);
    int H = HW / W;

    int ntx = (W + 15) / 16;
    int nty = (H + 15) / 16;

    dim3 grid(ntx, nty);
    fused_kernel<<<grid, 256>>>((float*)d_out, mean, qvec, svecb, sh, alphb, c2w,
                                H, W, N);
}

// round 7
// speedup vs baseline: 1.3241x; 1.0025x over previous
#include <cuda_runtime.h>
#include <math.h>

#define NMAX 1024
#define SMAX 256
#define L2E 1.4426950408889634f
#define TTHR 1.0e-4f
#define ECUT -26.6f

typedef unsigned long long ull;

// Per-gaussian params (unsorted, indexed by original gaussian id)
__device__ float4 g_cull[NMAX];   // mx, my, cut2, z_bits(as float)
__device__ float4 g_p0[NMAX];     // mx, my, A, B
__device__ float4 g_p1[NMAX];     // C, la, cr, cg
__device__ float  g_cb[NMAX];     // blue
__device__ int    g_arrive;       // producer-done counter (0 -> 4)
__device__ int    g_depart;       // reset bookkeeping

// ---------------------------------------------------------------------------
__device__ __forceinline__ void precompute_one(
    int n,
    const float* __restrict__ mean,
    const float* __restrict__ qvec,
    const float* __restrict__ svecb,
    const float* __restrict__ sh,
    const float* __restrict__ alphab,
    const float* __restrict__ c2w)
{
    float cw[16];
#pragma unroll
    for (int i = 0; i < 16; i++) cw[i] = __ldg(c2w + i);

    float d0 = mean[3 * n + 0] - cw[3];
    float d1 = mean[3 * n + 1] - cw[7];
    float d2 = mean[3 * n + 2] - cw[11];
    float px = cw[0] * d0 + cw[4] * d1 + cw[8]  * d2;
    float py = cw[1] * d0 + cw[5] * d1 + cw[9]  * d2;
    float pz = cw[2] * d0 + cw[6] * d1 + cw[10] * d2;

    float z = fmaxf(pz, 0.001f);
    float iz = __fdividef(1.f, z);
    float mx = px * iz;
    float my = py * iz;

    float qw = qvec[4 * n + 0], qx = qvec[4 * n + 1], qy = qvec[4 * n + 2], qz = qvec[4 * n + 3];
    float qn = rsqrtf(qw * qw + qx * qx + qy * qy + qz * qz);
    qw *= qn; qx *= qn; qy *= qn; qz *= qn;
    float R00 = 1.f - 2.f * (qy * qy + qz * qz);
    float R01 = 2.f * (qx * qy - qw * qz);
    float R02 = 2.f * (qx * qz + qw * qy);
    float R10 = 2.f * (qx * qy + qw * qz);
    float R11 = 1.f - 2.f * (qx * qx + qz * qz);
    float R12 = 2.f * (qy * qz - qw * qx);
    float R20 = 2.f * (qx * qz - qw * qy);
    float R21 = 2.f * (qy * qz + qw * qx);
    float R22 = 1.f - 2.f * (qx * qx + qy * qy);

    float s0 = __expf(svecb[3 * n + 0]);
    float s1 = __expf(svecb[3 * n + 1]);
    float s2 = __expf(svecb[3 * n + 2]);

    float M00 = R00 * s0, M01 = R01 * s1, M02 = R02 * s2;
    float M10 = R10 * s0, M11 = R11 * s1, M12 = R12 * s2;
    float M20 = R20 * s0, M21 = R21 * s1, M22 = R22 * s2;
    float v00 = M00 * M00 + M01 * M01 + M02 * M02;
    float v01 = M00 * M10 + M01 * M11 + M02 * M12;
    float v02 = M00 * M20 + M01 * M21 + M02 * M22;
    float v11 = M10 * M10 + M11 * M11 + M12 * M12;
    float v12 = M10 * M20 + M11 * M21 + M12 * M22;
    float v22 = M20 * M20 + M21 * M21 + M22 * M22;

    float W00 = cw[0], W01 = cw[4], W02 = cw[8];
    float W10 = cw[1], W11 = cw[5], W12 = cw[9];
    float W20 = cw[2], W21 = cw[6], W22 = cw[10];

    float t00 = W00 * v00 + W01 * v01 + W02 * v02;
    float t01 = W00 * v01 + W01 * v11 + W02 * v12;
    float t02 = W00 * v02 + W01 * v12 + W02 * v22;
    float t10 = W10 * v00 + W11 * v01 + W12 * v02;
    float t11 = W10 * v01 + W11 * v11 + W12 * v12;
    float t12 = W10 * v02 + W11 * v12 + W12 * v22;
    float t20 = W20 * v00 + W21 * v01 + W22 * v02;
    float t21 = W20 * v01 + W21 * v11 + W22 * v12;
    float t22 = W20 * v02 + W21 * v12 + W22 * v22;

    float c00 = t00 * W00 + t01 * W01 + t02 * W02;
    float c01 = t00 * W10 + t01 * W11 + t02 * W12;
    float c02 = t00 * W20 + t01 * W21 + t02 * W22;
    float c11 = t10 * W10 + t11 * W11 + t12 * W12;
    float c12 = t10 * W20 + t11 * W21 + t12 * W22;
    float c22 = t20 * W20 + t21 * W21 + t22 * W22;

    float iz2 = iz * iz;
    float j02 = -px * iz2;
    float j12 = -py * iz2;
    float r0a = iz * c00 + j02 * c02;
    float r0b = iz * c01 + j02 * c12;
    float r0c = iz * c02 + j02 * c22;
    float r1b = iz * c11 + j12 * c12;
    float r1c = iz * c12 + j12 * c22;
    float a2d = r0a * iz + r0c * j02 + 1e-8f;
    float b2d = r0b * iz + r0c * j12;
    float c2d = r1b * iz + r1c * j12 + 1e-8f;

    float idet = __fdividef(1.f, a2d * c2d - b2d * b2d);
    float ia = c2d * idet;
    float ib = -b2d * idet;
    float ic = a2d * idet;

    float A = -0.5f * L2E * ia;
    float B = -L2E * ib;
    float C = -0.5f * L2E * ic;

    float alpha = __fdividef(1.f, 1.f + __expf(-alphab[n]));
    float la = __log2f(alpha);

    float mid = 0.5f * (ia + ic);
    float dif = 0.5f * (ia - ic);
    float disc = sqrtf(fmaxf(dif * dif + ib * ib, 0.f));
    float lam = mid - disc;
    float cut2 = (la <= ECUT) ? -1.f
                              : __fdividef(la - ECUT, 0.5f * L2E * fmaxf(lam, 1e-30f));

    const float SHB = 0.28209479177387814f;
    float cr = __fdividef(1.f, 1.f + __expf(-SHB * sh[n * 27 + 0]));
    float cg = __fdividef(1.f, 1.f + __expf(-SHB * sh[n * 27 + 9]));
    float cb = __fdividef(1.f, 1.f + __expf(-SHB * sh[n * 27 + 18]));

    g_cull[n] = make_float4(mx, my, cut2, __uint_as_float(__float_as_uint(z)));
    g_p0[n]   = make_float4(mx, my, A, B);
    g_p1[n]   = make_float4(C, la, cr, cg);
    g_cb[n]   = cb;
}

// ---------------------------------------------------------------------------
// Fused kernel: blocks 0..3 precompute + signal; all blocks wait for the 4
// producer signals only, then render their own 16x16 tile.
// ---------------------------------------------------------------------------
__global__ void __launch_bounds__(256) fused_kernel(
    float* __restrict__ out,
    const float* __restrict__ mean,
    const float* __restrict__ qvec,
    const float* __restrict__ svecb,
    const float* __restrict__ sh,
    const float* __restrict__ alphab,
    const float* __restrict__ c2w,
    int H, int W, int N)
{
    __shared__ ull    skey[NMAX];     // 8KB
    __shared__ float4 f0[SMAX];       // 4KB
    __shared__ float4 f1[SMAX];       // 4KB
    __shared__ float  fcb[SMAX];      // 1KB
    __shared__ int    s_w[9];

    int tid = threadIdx.x;
    int bid = blockIdx.y * gridDim.x + blockIdx.x;
    int nBlocks = gridDim.x * gridDim.y;

    // ---- phase 1: precompute (blocks 0..3 = first 1024 threads) ----
    if (bid < 4) {
        int n = bid * 256 + tid;
        if (n < N) precompute_one(n, mean, qvec, svecb, sh, alphab, c2w);
        __syncthreads();
        if (tid == 0) {
            __threadfence();               // release: params visible before signal
            atomicAdd(&g_arrive, 1);
        }
    }

    // ---- wait for the 4 producer blocks only ----
    if (tid == 0) {
        while (*(volatile int*)&g_arrive < 4) __nanosleep(32);
    }
    __syncthreads();
    __threadfence();                       // acquire

    // ---- phase 2: render this block's tile ----
    int lane = tid & 31;
    int wid = tid >> 5;
    int tx = tid & 15;
    int ty = tid >> 4;
    int tbx = blockIdx.x;
    int tby = blockIdx.y;
    int pxi = tbx * 16 + tx;
    int pyi = tby * 16 + ty;

    float invW = 1.f / (float)W;
    float pxc = ((float)pxi + 0.5f - 0.5f * (float)W) * invW;
    float pyc = ((float)pyi + 0.5f - 0.5f * (float)H) * invW;
    float xmin = ((float)(tbx * 16)      + 0.5f - 0.5f * (float)W) * invW;
    float xmax = ((float)(tbx * 16 + 15) + 0.5f - 0.5f * (float)W) * invW;
    float ymin = ((float)(tby * 16)      + 0.5f - 0.5f * (float)H) * invW;
    float ymax = ((float)(tby * 16 + 15) + 0.5f - 0.5f * (float)H) * invW;

    // ---- cull: 4 contiguous gaussians per thread ----
    ull lk[4];
    int li[4];
    int cnt = 0;
#pragma unroll
    for (int r = 0; r < 4; r++) {
        int i = tid * 4 + r;
        if (i < N) {
            float4 c = g_cull[i];
            float ddx = fmaxf(fmaxf(xmin - c.x, c.x - xmax), 0.f);
            float ddy = fmaxf(fmaxf(ymin - c.y, c.y - ymax), 0.f);
            if (ddx * ddx + ddy * ddy <= c.z) {
                lk[cnt] = ((ull)__float_as_uint(c.w) << 32) | (unsigned)i;
                li[cnt] = i;
                cnt++;
            }
        }
    }

    // ---- block exclusive scan ----
    int incl = cnt;
#pragma unroll
    for (int d = 1; d < 32; d <<= 1) {
        int v = __shfl_up_sync(0xFFFFFFFFu, incl, d);
        if (lane >= d) incl += v;
    }
    if (lane == 31) s_w[wid] = incl;
    __syncthreads();
    if (tid == 0) {
        int s = 0;
#pragma unroll
        for (int w = 0; w < 8; w++) { int v = s_w[w]; s_w[w] = s; s += v; }
        s_w[8] = s;
    }
    __syncthreads();
    int base = s_w[wid] + incl - cnt;
    int total = s_w[8];

    for (int j = 0; j < cnt; j++) skey[base + j] = lk[j];
    __syncthreads();

    // ---- ranks (keys unique -> permutation) ----
    int rk[4];
    for (int j = 0; j < cnt; j++) {
        ull mine = lk[j];
        int r = 0;
        for (int k = 0; k < total; k++) r += (skey[k] < mine);
        rk[j] = r;
    }

    // ---- chunked staged composite ----
    float T = 1.f, ar = 0.f, ag = 0.f, ab = 0.f;
    for (int cbase = 0; cbase < total; cbase += SMAX) {
        int cn = min(SMAX, total - cbase);
        for (int j = 0; j < cnt; j++) {
            int r = rk[j] - cbase;
            if ((unsigned)r < (unsigned)SMAX) {
                int idx = li[j];
                f0[r]  = g_p0[idx];
                f1[r]  = g_p1[idx];
                fcb[r] = g_cb[idx];
            }
        }
        __syncthreads();

        if (T > TTHR) {
            int Me = cn & ~1;
            int k = 0;
            for (; k < Me; k += 2) {
                float4 p0a = f0[k],     p1a = f1[k];
                float4 p0b = f0[k + 1], p1b = f1[k + 1];
                float cba = fcb[k], cbb = fcb[k + 1];
                float dxa = pxc - p0a.x, dya = pyc - p0a.y;
                float dxb = pxc - p0b.x, dyb = pyc - p0b.y;
                float ea = fmaf(p0a.z * dxa, dxa, fmaf(p0a.w * dxa, dya, p1a.x * dya * dya)) + p1a.y;
                float eb = fmaf(p0b.z * dxb, dxb, fmaf(p0b.w * dxb, dyb, p1b.x * dyb * dyb)) + p1b.y;
                float wa, wb;
                asm("ex2.approx.ftz.f32 %0, %1;" : "=f"(wa) : "f"(ea));
                asm("ex2.approx.ftz.f32 %0, %1;" : "=f"(wb) : "f"(eb));
                float wTa = wa * T;
                ar = fmaf(wTa, p1a.z, ar);
                ag = fmaf(wTa, p1a.w, ag);
                ab = fmaf(wTa, cba, ab);
                float T1 = T * (1.f - fminf(wa, 0.9999f));
                if (T1 > TTHR) {
                    float wTb = wb * T1;
                    ar = fmaf(wTb, p1b.z, ar);
                    ag = fmaf(wTb, p1b.w, ag);
                    ab = fmaf(wTb, cbb, ab);
                    T = T1 * (1.f - fminf(wb, 0.9999f));
                    if (T <= TTHR) break;
                } else {
                    T = T1;
                    break;
                }
            }
            if (k == Me && Me < cn && T > TTHR) {
                float4 p0a = f0[Me], p1a = f1[Me];
                float cba = fcb[Me];
                float dxa = pxc - p0a.x, dya = pyc - p0a.y;
                float ea = fmaf(p0a.z * dxa, dxa, fmaf(p0a.w * dxa, dya, p1a.x * dya * dya)) + p1a.y;
                float wa;
                asm("ex2.approx.ftz.f32 %0, %1;" : "=f"(wa) : "f"(ea));
                float wTa = wa * T;
                ar = fmaf(wTa, p1a.z, ar);
                ag = fmaf(wTa, p1a.w, ag);
                ab = fmaf(wTa, cba, ab);
                T = T * (1.f - fminf(wa, 0.9999f));
            }
        }
        if (__syncthreads_and(T <= TTHR)) break;
    }

    if (pxi < W && pyi < H) {
        int o = (pyi * W + pxi) * 3;
        out[o + 0] = ar;
        out[o + 1] = ag;
        out[o + 2] = ab;
    }

    // ---- self-resetting counters (last block zeroes both) ----
    if (tid == 0) {
        int d = atomicAdd(&g_depart, 1);
        if (d == nBlocks - 1) {
            *(volatile int*)&g_arrive = 0;
            *(volatile int*)&g_depart = 0;
            __threadfence();
        }
    }
}

// ---------------------------------------------------------------------------
extern "C" void kernel_launch(void* const* d_in, const int* in_sizes, int n_in,
                              void* d_out, int out_size)
{
    const float* mean  = (const float*)d_in[0];
    const float* qvec  = (const float*)d_in[1];
    const float* svecb = (const float*)d_in[2];
    const float* sh    = (const float*)d_in[3];
    const float* alphb = (const float*)d_in[4];
    const float* c2w   = (const float*)d_in[5];

    int N = in_sizes[0] / 3;
    if (N > NMAX) N = NMAX;
    int HW = out_size / 3;
    int W = (int)(sqrtf((float)HW) + 0.5f);
    int H = HW / W;

    int ntx = (W + 15) / 16;
    int nty = (H + 15) / 16;

    dim3 grid(ntx, nty);
    fused_kernel<<<grid, 256>>>((float*)d_out, mean, qvec, svecb, sh, alphb, c2w,
                                H, W, N);
}